// round 14
// baseline (speedup 1.0000x reference)
#include <cuda_runtime.h>
#include <cuda_bf16.h>

// Problem constants
#define BATCH   8
#define SEQ     1024
#define EMB     768
#define NHEADS  12
#define HDIM    64
#define ATTND   (NHEADS*HDIM)       // 768
#define QKVD    (3*ATTND)           // 2304

// Scratch (device globals — allocation-free)
__device__ float g_qkv [BATCH*SEQ*QKVD];   // [B,N,2304]
__device__ float g_attn[BATCH*SEQ*ATTND];  // [B,N,768]

// ---------------------------------------------------------------------------
// SGEMM: C[M,N] = A[M,K] * B[K,N] (+bias). M%128==0, N%128==0, K%16==0.
// 256 threads, 128x128 block tile, 8x8 per thread (2x2 of 4x4), BK=16.
// ---------------------------------------------------------------------------
__global__ void __launch_bounds__(256, 2)
sgemm128(const float* __restrict__ A, const float* __restrict__ B,
         float* __restrict__ C, const float* __restrict__ bias,
         int M, int N, int K)
{
    const int bx  = blockIdx.x;       // N tile
    const int by  = blockIdx.y;       // M tile
    const int tid = threadIdx.x;
    const int tx  = tid & 15;         // 0..15
    const int ty  = tid >> 4;         // 0..15

    __shared__ float As[16][132];     // A transposed: As[k][m], pad -> <=2-way
    __shared__ float Bs[16][128];     // Bs[k][n]

    const int arow = tid >> 2;        // 0..63
    const int acol = (tid & 3) * 4;   // 0,4,8,12
    const int brow = tid >> 5;        // 0..7
    const int bcol = (tid & 31) * 4;  // 0..124

    const float* Ag = A + (long)(by*128 + arow) * K + acol;
    const float* Bg = B + (long)brow * N + (long)bx*128 + bcol;

    float acc[8][8];
    #pragma unroll
    for (int i = 0; i < 8; i++)
        #pragma unroll
        for (int j = 0; j < 8; j++) acc[i][j] = 0.f;

    for (int k0 = 0; k0 < K; k0 += 16) {
        // Load A tile (transposed store)
        #pragma unroll
        for (int p = 0; p < 2; p++) {
            float4 a4 = *(const float4*)(Ag + (long)p*64*K + k0);
            As[acol+0][arow + 64*p] = a4.x;
            As[acol+1][arow + 64*p] = a4.y;
            As[acol+2][arow + 64*p] = a4.z;
            As[acol+3][arow + 64*p] = a4.w;
        }
        // Load B tile (direct)
        #pragma unroll
        for (int p = 0; p < 2; p++) {
            *(float4*)&Bs[brow + 8*p][bcol] =
                *(const float4*)(Bg + (long)(k0 + 8*p) * N);
        }
        __syncthreads();

        #pragma unroll
        for (int k = 0; k < 16; k++) {
            float a[8], bb[8];
            *(float4*)&a[0]  = *(const float4*)&As[k][ty*4];
            *(float4*)&a[4]  = *(const float4*)&As[k][64 + ty*4];
            *(float4*)&bb[0] = *(const float4*)&Bs[k][tx*4];
            *(float4*)&bb[4] = *(const float4*)&Bs[k][64 + tx*4];
            #pragma unroll
            for (int i = 0; i < 8; i++)
                #pragma unroll
                for (int j = 0; j < 8; j++)
                    acc[i][j] = fmaf(a[i], bb[j], acc[i][j]);
        }
        __syncthreads();
    }

    // Epilogue (coalesced float4 stores, optional bias)
    const int crow0 = by*128 + ty*4;
    const int ccol0 = bx*128 + tx*4;
    #pragma unroll
    for (int ih = 0; ih < 2; ih++) {
        #pragma unroll
        for (int i = 0; i < 4; i++) {
            const int row = crow0 + 64*ih + i;
            #pragma unroll
            for (int jh = 0; jh < 2; jh++) {
                const int col = ccol0 + 64*jh;
                float4 r;
                r.x = acc[ih*4+i][jh*4+0];
                r.y = acc[ih*4+i][jh*4+1];
                r.z = acc[ih*4+i][jh*4+2];
                r.w = acc[ih*4+i][jh*4+3];
                if (bias) {
                    float4 bv = *(const float4*)(bias + col);
                    r.x += bv.x; r.y += bv.y; r.z += bv.z; r.w += bv.w;
                }
                *(float4*)(C + (long)row * N + col) = r;
            }
        }
    }
}

// ---------------------------------------------------------------------------
// Flash attention: one block = (b, h, 64 q-rows). KV tiles of 64, online
// softmax. 256 threads (16x16), each owns a 4x4 of the 64x64 S / O tiles.
// Dynamic smem: Qt[64][68] + Kt[64][68] + Vs[64][64] + Ps[64][64] = 66 KB.
// ---------------------------------------------------------------------------
__global__ void __launch_bounds__(256)
attn_kernel(const float* __restrict__ qkv, float* __restrict__ out)
{
    const int qt  = blockIdx.x;  // q tile 0..15
    const int h   = blockIdx.y;  // head 0..11
    const int b   = blockIdx.z;  // batch 0..7
    const int tid = threadIdx.x;
    const int tx  = tid & 15;
    const int ty  = tid >> 4;

    extern __shared__ float sm[];
    float* Qt = sm;               // [64][68]  Qt[d][q]
    float* Kt = Qt + 64*68;       // [64][68]  Kt[d][k]
    float* Vs = Kt + 64*68;       // [64][64]  Vs[k][d]
    float* Ps = Vs + 64*64;       // [64][64]  Ps[q][k]

    const float scale = 0.125f;   // 1/sqrt(64)
    const float* Qg = qkv + ((long)b*SEQ + qt*64) * QKVD + h*HDIM;
    const float* Kg = qkv + (long)b*SEQ*QKVD + ATTND   + h*HDIM;
    const float* Vg = qkv + (long)b*SEQ*QKVD + 2*ATTND + h*HDIM;

    // Load Q tile transposed
    {
        const int r = tid >> 4, c = tid & 15;
        #pragma unroll
        for (int p = 0; p < 4; p++) {
            const int row = r + 16*p;
            float4 v = *(const float4*)(Qg + (long)row*QKVD + 4*c);
            Qt[(4*c+0)*68 + row] = v.x;
            Qt[(4*c+1)*68 + row] = v.y;
            Qt[(4*c+2)*68 + row] = v.z;
            Qt[(4*c+3)*68 + row] = v.w;
        }
    }

    float o[4][4];
    float m[4], l[4];
    #pragma unroll
    for (int i = 0; i < 4; i++) {
        m[i] = -1e30f; l[i] = 0.f;
        #pragma unroll
        for (int j = 0; j < 4; j++) o[i][j] = 0.f;
    }

    for (int kt0 = 0; kt0 < SEQ; kt0 += 64) {
        __syncthreads();   // previous iter done with Kt/Vs/Ps; Qt writes fenced by next sync
        // Load K (transposed) and V tiles
        {
            const int r = tid >> 4, c = tid & 15;
            #pragma unroll
            for (int p = 0; p < 4; p++) {
                const int row = r + 16*p;
                float4 k4 = *(const float4*)(Kg + (long)(kt0+row)*QKVD + 4*c);
                Kt[(4*c+0)*68 + row] = k4.x;
                Kt[(4*c+1)*68 + row] = k4.y;
                Kt[(4*c+2)*68 + row] = k4.z;
                Kt[(4*c+3)*68 + row] = k4.w;
                float4 v4 = *(const float4*)(Vg + (long)(kt0+row)*QKVD + 4*c);
                *(float4*)(Vs + row*64 + 4*c) = v4;
            }
        }
        __syncthreads();

        // S = Q K^T (thread: rows 4ty..+3, cols 4tx..+3)
        float s[4][4];
        #pragma unroll
        for (int i = 0; i < 4; i++)
            #pragma unroll
            for (int j = 0; j < 4; j++) s[i][j] = 0.f;

        #pragma unroll 8
        for (int d = 0; d < 64; d++) {
            float4 aq = *(const float4*)(Qt + d*68 + 4*ty);
            float4 bk = *(const float4*)(Kt + d*68 + 4*tx);
            const float a_[4] = {aq.x, aq.y, aq.z, aq.w};
            const float b_[4] = {bk.x, bk.y, bk.z, bk.w};
            #pragma unroll
            for (int i = 0; i < 4; i++)
                #pragma unroll
                for (int j = 0; j < 4; j++)
                    s[i][j] = fmaf(a_[i], b_[j], s[i][j]);
        }

        // Online softmax update per q row; row stats across the 16 tx lanes
        #pragma unroll
        for (int i = 0; i < 4; i++) {
            float tmax = -1e30f;
            #pragma unroll
            for (int j = 0; j < 4; j++) {
                s[i][j] *= scale;
                tmax = fmaxf(tmax, s[i][j]);
            }
            #pragma unroll
            for (int off = 8; off > 0; off >>= 1)
                tmax = fmaxf(tmax, __shfl_xor_sync(0xffffffffu, tmax, off, 16));
            const float newm = fmaxf(m[i], tmax);
            const float corr = __expf(m[i] - newm);
            m[i] = newm;
            l[i] *= corr;
            #pragma unroll
            for (int j = 0; j < 4; j++) o[i][j] *= corr;
            float rs = 0.f;
            #pragma unroll
            for (int j = 0; j < 4; j++) {
                s[i][j] = __expf(s[i][j] - newm);
                rs += s[i][j];
            }
            #pragma unroll
            for (int off = 8; off > 0; off >>= 1)
                rs += __shfl_xor_sync(0xffffffffu, rs, off, 16);
            l[i] += rs;
            *(float4*)(Ps + (4*ty+i)*64 + 4*tx) =
                make_float4(s[i][0], s[i][1], s[i][2], s[i][3]);
        }
        __syncthreads();

        // O += P V  (4 k-columns per step, all float4 reads)
        #pragma unroll 4
        for (int k4 = 0; k4 < 16; k4++) {
            float4 pr[4], vr[4];
            #pragma unroll
            for (int i = 0; i < 4; i++)
                pr[i] = *(const float4*)(Ps + (4*ty+i)*64 + 4*k4);
            #pragma unroll
            for (int kk = 0; kk < 4; kk++)
                vr[kk] = *(const float4*)(Vs + (4*k4+kk)*64 + 4*tx);
            #pragma unroll
            for (int i = 0; i < 4; i++) {
                const float p_[4] = {pr[i].x, pr[i].y, pr[i].z, pr[i].w};
                #pragma unroll
                for (int kk = 0; kk < 4; kk++) {
                    const float v_[4] = {vr[kk].x, vr[kk].y, vr[kk].z, vr[kk].w};
                    #pragma unroll
                    for (int j = 0; j < 4; j++)
                        o[i][j] = fmaf(p_[kk], v_[j], o[i][j]);
                }
            }
        }
    }

    // Normalize and write [B,N,ATTND] with head offset (== transpose+reshape)
    float* Og = out + ((long)b*SEQ + qt*64) * ATTND + h*HDIM;
    #pragma unroll
    for (int i = 0; i < 4; i++) {
        const float inv = 1.f / l[i];
        float4 r = make_float4(o[i][0]*inv, o[i][1]*inv, o[i][2]*inv, o[i][3]*inv);
        *(float4*)(Og + (long)(4*ty+i)*ATTND + 4*tx) = r;
    }
}

// ---------------------------------------------------------------------------
extern "C" void kernel_launch(void* const* d_in, const int* in_sizes, int n_in,
                              void* d_out, int out_size)
{
    const float* x     = (const float*)d_in[0];  // [8,1024,768]
    const float* w_qkv = (const float*)d_in[1];  // [768,2304]
    const float* w_out = (const float*)d_in[2];  // [768,768]
    const float* b_out = (const float*)d_in[3];  // [768]
    float* outp        = (float*)d_out;          // [8,1024,768]

    float* qkv_ptr  = nullptr;
    float* attn_ptr = nullptr;
    cudaGetSymbolAddress((void**)&qkv_ptr,  g_qkv);
    cudaGetSymbolAddress((void**)&attn_ptr, g_attn);

    const int M = BATCH * SEQ;   // 8192

    // 1) QKV projection: [8192,768] x [768,2304]
    {
        dim3 grid(QKVD/128, M/128);
        sgemm128<<<grid, 256>>>(x, w_qkv, qkv_ptr, nullptr, M, QKVD, EMB);
    }

    // 2) Attention
    {
        const int smem = (2*64*68 + 2*64*64) * (int)sizeof(float); // 67584 B
        cudaFuncSetAttribute(attn_kernel,
                             cudaFuncAttributeMaxDynamicSharedMemorySize, smem);
        dim3 grid(SEQ/64, NHEADS, BATCH);  // (16,12,8)
        attn_kernel<<<grid, 256, smem>>>(qkv_ptr, attn_ptr);
    }

    // 3) Output projection + bias: [8192,768] x [768,768]
    {
        dim3 grid(EMB/128, M/128);
        sgemm128<<<grid, 256>>>(attn_ptr, w_out, outp, b_out, M, EMB, ATTND);
    }
}

// round 16
// speedup vs baseline: 1.2698x; 1.2698x over previous
#include <cuda_runtime.h>
#include <cuda_bf16.h>
#include <cstdint>

// Problem constants
#define BATCH   8
#define SEQ     1024
#define EMB     768
#define NHEADS  12
#define HDIM    64
#define ATTND   (NHEADS*HDIM)       // 768
#define QKVD    (3*ATTND)           // 2304
#define MTOT    (BATCH*SEQ)         // 8192

// ---------------- Scratch (device globals — allocation-free) ----------------
__device__ float         g_qkv   [MTOT*QKVD];     // fp32 QKV (attention input)
__device__ __nv_bfloat16 g_xh    [MTOT*EMB];
__device__ __nv_bfloat16 g_xl    [MTOT*EMB];
__device__ __nv_bfloat16 g_wqkvTh[QKVD*EMB];      // w_qkv^T [N=2304][K=768]
__device__ __nv_bfloat16 g_wqkvTl[QKVD*EMB];
__device__ __nv_bfloat16 g_woutTh[EMB*ATTND];     // w_out^T [N=768][K=768]
__device__ __nv_bfloat16 g_woutTl[EMB*ATTND];
__device__ __nv_bfloat16 g_ah    [MTOT*ATTND];    // attention out hi
__device__ __nv_bfloat16 g_al    [MTOT*ATTND];    // attention out lo

// ---------------------------- helpers --------------------------------------
static __device__ __forceinline__ uint32_t smem_u32(const void* p) {
    uint32_t a;
    asm("{ .reg .u64 t; cvta.to.shared.u64 t, %1; cvt.u32.u64 %0, t; }"
        : "=r"(a) : "l"(p));
    return a;
}

static __device__ __forceinline__ void ldsm4(uint32_t* r, uint32_t addr) {
    asm volatile("ldmatrix.sync.aligned.m8n8.x4.shared.b16 {%0,%1,%2,%3}, [%4];"
                 : "=r"(r[0]), "=r"(r[1]), "=r"(r[2]), "=r"(r[3]) : "r"(addr));
}

static __device__ __forceinline__ void mma_bf16(float* c, const uint32_t* a,
                                                const uint32_t* b) {
    asm volatile(
        "mma.sync.aligned.m16n8k16.row.col.f32.bf16.bf16.f32 "
        "{%0,%1,%2,%3},{%4,%5,%6,%7},{%8,%9},{%0,%1,%2,%3};"
        : "+f"(c[0]), "+f"(c[1]), "+f"(c[2]), "+f"(c[3])
        : "r"(a[0]), "r"(a[1]), "r"(a[2]), "r"(a[3]), "r"(b[0]), "r"(b[1]));
}

// ---------------------------------------------------------------------------
// Split fp32 -> bf16 hi/lo (float4 vectorized). n4 = n/4.
// ---------------------------------------------------------------------------
__global__ void split_kernel(const float* __restrict__ in,
                             __nv_bfloat16* __restrict__ hi,
                             __nv_bfloat16* __restrict__ lo, int n4)
{
    int i = blockIdx.x * blockDim.x + threadIdx.x;
    if (i >= n4) return;
    float4 v = ((const float4*)in)[i];
    union { __nv_bfloat16 b[4]; uint2 u; } H, L;
    H.b[0] = __float2bfloat16(v.x); L.b[0] = __float2bfloat16(v.x - __bfloat162float(H.b[0]));
    H.b[1] = __float2bfloat16(v.y); L.b[1] = __float2bfloat16(v.y - __bfloat162float(H.b[1]));
    H.b[2] = __float2bfloat16(v.z); L.b[2] = __float2bfloat16(v.z - __bfloat162float(H.b[2]));
    H.b[3] = __float2bfloat16(v.w); L.b[3] = __float2bfloat16(v.w - __bfloat162float(H.b[3]));
    ((uint2*)hi)[i] = H.u;
    ((uint2*)lo)[i] = L.u;
}

// ---------------------------------------------------------------------------
// Transpose + split: w[K][N] fp32 -> wT hi/lo [N][K] bf16.
// ---------------------------------------------------------------------------
__global__ void transpose_split(const float* __restrict__ w,
                                __nv_bfloat16* __restrict__ th,
                                __nv_bfloat16* __restrict__ tl, int K, int N)
{
    __shared__ float tile[32][33];
    const int n0 = blockIdx.x * 32;
    const int k0 = blockIdx.y * 32;
    const int tx = threadIdx.x, ty = threadIdx.y; // 32 x 8
    #pragma unroll
    for (int p = 0; p < 4; p++)
        tile[ty + 8*p][tx] = w[(long)(k0 + ty + 8*p) * N + n0 + tx];
    __syncthreads();
    #pragma unroll
    for (int p = 0; p < 4; p++) {
        float f = tile[tx][ty + 8*p];
        __nv_bfloat16 h = __float2bfloat16(f);
        long o = (long)(n0 + ty + 8*p) * K + k0 + tx;
        th[o] = h;
        tl[o] = __float2bfloat16(f - __bfloat162float(h));
    }
}

// ---------------------------------------------------------------------------
// mma.sync split-bf16 GEMM: C[M,N] = A[M,K] * B^T   (B stored [N][K] K-major)
// D = Ah*Bh + Ah*Bl + Al*Bh, fp32 accumulation in registers.
// CTA tile 128x128, BK=32, 8 warps (64x32 each), double-buffered smem.
// smem rows pitched to 80B (64B data + 16B pad) -> ldmatrix conflict-free.
// ---------------------------------------------------------------------------
#define PITCH    80                     // bytes per smem row (32 bf16 + pad)
#define TILE_B   (128*PITCH)            // 10240 B per tile
#define STAGE_B  (4*TILE_B)             // Ah, Al, Bh, Bl = 40960 B
#define GEMM_SMEM (2*STAGE_B)           // 81920 B

__global__ void __launch_bounds__(256, 1)
gemm_mma(const __nv_bfloat16* __restrict__ Ah, const __nv_bfloat16* __restrict__ Al,
         const __nv_bfloat16* __restrict__ Bh, const __nv_bfloat16* __restrict__ Bl,
         float* __restrict__ C, const float* __restrict__ biasp, int N, int K)
{
    extern __shared__ char smem[];
    const int tid  = threadIdx.x;
    const int wid  = tid >> 5;
    const int lane = tid & 31;
    const int wm   = wid >> 2;     // 0..1  (64 rows each)
    const int wn   = wid & 3;      // 0..3  (32 cols each)
    const int bx = blockIdx.x, by = blockIdx.y;

    const uint32_t sbase = smem_u32(smem);

    const char* gsrc[4] = {
        (const char*)(Ah + (long)by * 128 * K),
        (const char*)(Al + (long)by * 128 * K),
        (const char*)(Bh + (long)bx * 128 * K),
        (const char*)(Bl + (long)bx * 128 * K) };
    const long rsb = (long)K * 2;

    // global->smem: per tile 128 rows x 64B; idx -> (row=idx>>2, 16B chunk=idx&3)
    auto load_stage = [&](int s, int k0) {
        char* sb = smem + s * STAGE_B;
        #pragma unroll
        for (int t = 0; t < 4; t++) {
            const char* src = gsrc[t] + (long)k0 * 2;
            char* dst = sb + t * TILE_B;
            #pragma unroll
            for (int i = 0; i < 2; i++) {
                int idx = tid + i * 256;          // 0..511
                int row = idx >> 2;
                int cb  = (idx & 3) * 16;
                uint4 v = *(const uint4*)(src + (long)row * rsb + cb);
                *(uint4*)(dst + row * PITCH + cb) = v;
            }
        }
    };

    // per-thread ldmatrix offsets (bytes)
    const uint32_t a_off = (uint32_t)(wm*64 + (lane & 15)) * PITCH + ((lane >> 4) << 4);
    const uint32_t b_off = (uint32_t)(wn*32 + (lane & 7) + ((lane >> 4) << 3)) * PITCH
                         + (((lane >> 3) & 1) << 4);

    float acc[4][4][4];
    #pragma unroll
    for (int mi = 0; mi < 4; mi++)
        #pragma unroll
        for (int ni = 0; ni < 4; ni++)
            #pragma unroll
            for (int q = 0; q < 4; q++) acc[mi][ni][q] = 0.f;

    const int NI = K / 32;
    load_stage(0, 0);

    for (int it = 0; it < NI; it++) {
        __syncthreads();
        if (it + 1 < NI) load_stage((it + 1) & 1, (it + 1) * 32);

        const uint32_t sb = sbase + (uint32_t)(it & 1) * STAGE_B;
        #pragma unroll
        for (int kh = 0; kh < 2; kh++) {
            uint32_t ah[4][4], al[4][4], bh[2][4], bl[2][4];
            #pragma unroll
            for (int mi = 0; mi < 4; mi++) {
                const uint32_t ao = sb + a_off + mi * (16*PITCH) + kh * 32;
                ldsm4(ah[mi], ao);
                ldsm4(al[mi], ao + TILE_B);
            }
            #pragma unroll
            for (int nj = 0; nj < 2; nj++) {
                const uint32_t bo = sb + 2*TILE_B + b_off + nj * (16*PITCH) + kh * 32;
                ldsm4(bh[nj], bo);
                ldsm4(bl[nj], bo + TILE_B);
            }
            #pragma unroll
            for (int mi = 0; mi < 4; mi++)
                #pragma unroll
                for (int ni = 0; ni < 4; ni++) {
                    const uint32_t* bhp = &bh[ni >> 1][(ni & 1) * 2];
                    const uint32_t* blp = &bl[ni >> 1][(ni & 1) * 2];
                    mma_bf16(acc[mi][ni], ah[mi], bhp);
                    mma_bf16(acc[mi][ni], ah[mi], blp);
                    mma_bf16(acc[mi][ni], al[mi], bhp);
                }
        }
    }

    // Epilogue: fragment layout m16n8 -> rows (lane/4, +8), cols 2*(lane%4)
    const int r0 = by * 128 + wm * 64 + (lane >> 2);
    const int c0 = bx * 128 + wn * 32 + ((lane & 3) << 1);
    #pragma unroll
    for (int mi = 0; mi < 4; mi++) {
        #pragma unroll
        for (int ni = 0; ni < 4; ni++) {
            const int row = r0 + mi * 16;
            const int col = c0 + ni * 8;
            float bx0 = 0.f, bx1 = 0.f;
            if (biasp) { bx0 = biasp[col]; bx1 = biasp[col + 1]; }
            float2 v0 = make_float2(acc[mi][ni][0] + bx0, acc[mi][ni][1] + bx1);
            float2 v1 = make_float2(acc[mi][ni][2] + bx0, acc[mi][ni][3] + bx1);
            *(float2*)(C + (long)row * N + col)       = v0;
            *(float2*)(C + (long)(row + 8) * N + col) = v1;
        }
    }
}

// ---------------------------------------------------------------------------
// Flash attention (fp32 SIMT, passing version; emits bf16 hi/lo)
// ---------------------------------------------------------------------------
__global__ void __launch_bounds__(256)
attn_kernel(const float* __restrict__ qkv,
            __nv_bfloat16* __restrict__ outh, __nv_bfloat16* __restrict__ outl)
{
    const int qt  = blockIdx.x;
    const int h   = blockIdx.y;
    const int b   = blockIdx.z;
    const int tid = threadIdx.x;
    const int tx  = tid & 15;
    const int ty  = tid >> 4;

    extern __shared__ float sm[];
    float* Qt = sm;               // [64][68]
    float* Kt = Qt + 64*68;       // [64][68]
    float* Vs = Kt + 64*68;       // [64][64]
    float* Ps = Vs + 64*64;       // [64][64]

    const float scale = 0.125f;
    const float* Qg = qkv + ((long)b*SEQ + qt*64) * QKVD + h*HDIM;
    const float* Kg = qkv + (long)b*SEQ*QKVD + ATTND   + h*HDIM;
    const float* Vg = qkv + (long)b*SEQ*QKVD + 2*ATTND + h*HDIM;

    {
        const int r = tid >> 4, c = tid & 15;
        #pragma unroll
        for (int p = 0; p < 4; p++) {
            const int row = r + 16*p;
            float4 v = *(const float4*)(Qg + (long)row*QKVD + 4*c);
            Qt[(4*c+0)*68 + row] = v.x;
            Qt[(4*c+1)*68 + row] = v.y;
            Qt[(4*c+2)*68 + row] = v.z;
            Qt[(4*c+3)*68 + row] = v.w;
        }
    }

    float o[4][4];
    float m[4], l[4];
    #pragma unroll
    for (int i = 0; i < 4; i++) {
        m[i] = -1e30f; l[i] = 0.f;
        #pragma unroll
        for (int j = 0; j < 4; j++) o[i][j] = 0.f;
    }

    for (int kt0 = 0; kt0 < SEQ; kt0 += 64) {
        __syncthreads();
        {
            const int r = tid >> 4, c = tid & 15;
            #pragma unroll
            for (int p = 0; p < 4; p++) {
                const int row = r + 16*p;
                float4 k4 = *(const float4*)(Kg + (long)(kt0+row)*QKVD + 4*c);
                Kt[(4*c+0)*68 + row] = k4.x;
                Kt[(4*c+1)*68 + row] = k4.y;
                Kt[(4*c+2)*68 + row] = k4.z;
                Kt[(4*c+3)*68 + row] = k4.w;
                float4 v4 = *(const float4*)(Vg + (long)(kt0+row)*QKVD + 4*c);
                *(float4*)(Vs + row*64 + 4*c) = v4;
            }
        }
        __syncthreads();

        float s[4][4];
        #pragma unroll
        for (int i = 0; i < 4; i++)
            #pragma unroll
            for (int j = 0; j < 4; j++) s[i][j] = 0.f;

        #pragma unroll 8
        for (int d = 0; d < 64; d++) {
            float4 aq = *(const float4*)(Qt + d*68 + 4*ty);
            float4 bk = *(const float4*)(Kt + d*68 + 4*tx);
            const float a_[4] = {aq.x, aq.y, aq.z, aq.w};
            const float b_[4] = {bk.x, bk.y, bk.z, bk.w};
            #pragma unroll
            for (int i = 0; i < 4; i++)
                #pragma unroll
                for (int j = 0; j < 4; j++)
                    s[i][j] = fmaf(a_[i], b_[j], s[i][j]);
        }

        #pragma unroll
        for (int i = 0; i < 4; i++) {
            float tmax = -1e30f;
            #pragma unroll
            for (int j = 0; j < 4; j++) {
                s[i][j] *= scale;
                tmax = fmaxf(tmax, s[i][j]);
            }
            #pragma unroll
            for (int off = 8; off > 0; off >>= 1)
                tmax = fmaxf(tmax, __shfl_xor_sync(0xffffffffu, tmax, off, 16));
            const float newm = fmaxf(m[i], tmax);
            const float corr = __expf(m[i] - newm);
            m[i] = newm;
            l[i] *= corr;
            #pragma unroll
            for (int j = 0; j < 4; j++) o[i][j] *= corr;
            float rs = 0.f;
            #pragma unroll
            for (int j = 0; j < 4; j++) {
                s[i][j] = __expf(s[i][j] - newm);
                rs += s[i][j];
            }
            #pragma unroll
            for (int off = 8; off > 0; off >>= 1)
                rs += __shfl_xor_sync(0xffffffffu, rs, off, 16);
            l[i] += rs;
            *(float4*)(Ps + (4*ty+i)*64 + 4*tx) =
                make_float4(s[i][0], s[i][1], s[i][2], s[i][3]);
        }
        __syncthreads();

        #pragma unroll 4
        for (int k4 = 0; k4 < 16; k4++) {
            float4 pr[4], vr[4];
            #pragma unroll
            for (int i = 0; i < 4; i++)
                pr[i] = *(const float4*)(Ps + (4*ty+i)*64 + 4*k4);
            #pragma unroll
            for (int kk = 0; kk < 4; kk++)
                vr[kk] = *(const float4*)(Vs + (4*k4+kk)*64 + 4*tx);
            #pragma unroll
            for (int i = 0; i < 4; i++) {
                const float p_[4] = {pr[i].x, pr[i].y, pr[i].z, pr[i].w};
                #pragma unroll
                for (int kk = 0; kk < 4; kk++) {
                    const float v_[4] = {vr[kk].x, vr[kk].y, vr[kk].z, vr[kk].w};
                    #pragma unroll
                    for (int j = 0; j < 4; j++)
                        o[i][j] = fmaf(p_[kk], v_[j], o[i][j]);
                }
            }
        }
    }

    const long rbase = ((long)b*SEQ + qt*64) * ATTND + h*HDIM;
    #pragma unroll
    for (int i = 0; i < 4; i++) {
        const float inv = 1.f / l[i];
        float v0 = o[i][0]*inv, v1 = o[i][1]*inv, v2 = o[i][2]*inv, v3 = o[i][3]*inv;
        union { __nv_bfloat16 b[4]; uint2 u; } H, L;
        H.b[0] = __float2bfloat16(v0); L.b[0] = __float2bfloat16(v0 - __bfloat162float(H.b[0]));
        H.b[1] = __float2bfloat16(v1); L.b[1] = __float2bfloat16(v1 - __bfloat162float(H.b[1]));
        H.b[2] = __float2bfloat16(v2); L.b[2] = __float2bfloat16(v2 - __bfloat162float(H.b[2]));
        H.b[3] = __float2bfloat16(v3); L.b[3] = __float2bfloat16(v3 - __bfloat162float(H.b[3]));
        const long off = rbase + (long)(4*ty + i) * ATTND + 4*tx;
        *(uint2*)(outh + off) = H.u;
        *(uint2*)(outl + off) = L.u;
    }
}

// ---------------------------------------------------------------------------
extern "C" void kernel_launch(void* const* d_in, const int* in_sizes, int n_in,
                              void* d_out, int out_size)
{
    const float* x     = (const float*)d_in[0];
    const float* w_qkv = (const float*)d_in[1];
    const float* w_out = (const float*)d_in[2];
    const float* b_out = (const float*)d_in[3];
    float* outp        = (float*)d_out;

    float *qkv_p;
    __nv_bfloat16 *xh_p, *xl_p, *wqh_p, *wql_p, *woh_p, *wol_p, *ah_p, *al_p;
    cudaGetSymbolAddress((void**)&qkv_p, g_qkv);
    cudaGetSymbolAddress((void**)&xh_p,  g_xh);
    cudaGetSymbolAddress((void**)&xl_p,  g_xl);
    cudaGetSymbolAddress((void**)&wqh_p, g_wqkvTh);
    cudaGetSymbolAddress((void**)&wql_p, g_wqkvTl);
    cudaGetSymbolAddress((void**)&woh_p, g_woutTh);
    cudaGetSymbolAddress((void**)&wol_p, g_woutTl);
    cudaGetSymbolAddress((void**)&ah_p,  g_ah);
    cudaGetSymbolAddress((void**)&al_p,  g_al);

    // 0) Conversions
    {
        const int n4 = MTOT * EMB / 4;
        split_kernel<<<(n4 + 255) / 256, 256>>>(x, xh_p, xl_p, n4);
        dim3 tb(32, 8);
        transpose_split<<<dim3(QKVD/32, EMB/32), tb>>>(w_qkv, wqh_p, wql_p, EMB, QKVD);
        transpose_split<<<dim3(EMB/32,  EMB/32), tb>>>(w_out, woh_p, wol_p, EMB, EMB);
    }

    cudaFuncSetAttribute(gemm_mma, cudaFuncAttributeMaxDynamicSharedMemorySize, GEMM_SMEM);

    // 1) QKV projection: [8192,768] x [768,2304]
    gemm_mma<<<dim3(QKVD/128, MTOT/128), 256, GEMM_SMEM>>>(
        xh_p, xl_p, wqh_p, wql_p, qkv_p, nullptr, QKVD, EMB);

    // 2) Attention (fp32 SIMT), emits bf16 hi/lo
    {
        const int smem = (2*64*68 + 2*64*64) * (int)sizeof(float);
        cudaFuncSetAttribute(attn_kernel,
                             cudaFuncAttributeMaxDynamicSharedMemorySize, smem);
        dim3 grid(SEQ/64, NHEADS, BATCH);
        attn_kernel<<<grid, 256, smem>>>(qkv_p, ah_p, al_p);
    }

    // 3) Output projection + bias: [8192,768] x [768,768]
    gemm_mma<<<dim3(EMB/128, MTOT/128), 256, GEMM_SMEM>>>(
        ah_p, al_p, woh_p, wol_p, outp, b_out, EMB, ATTND);
}

// round 17
// speedup vs baseline: 1.2712x; 1.0011x over previous
#include <cuda_runtime.h>
#include <cuda_bf16.h>
#include <cstdint>

// Problem constants
#define BATCH   8
#define SEQ     1024
#define EMB     768
#define NHEADS  12
#define HDIM    64
#define ATTND   (NHEADS*HDIM)       // 768
#define QKVD    (3*ATTND)           // 2304
#define MTOT    (BATCH*SEQ)         // 8192

// ---------------- Scratch (device globals — allocation-free) ----------------
__device__ float         g_qkv   [MTOT*QKVD];     // fp32 QKV (attention input)
__device__ __nv_bfloat16 g_xh    [MTOT*EMB];
__device__ __nv_bfloat16 g_xl    [MTOT*EMB];
__device__ __nv_bfloat16 g_wqkvTh[QKVD*EMB];      // w_qkv^T [N=2304][K=768]
__device__ __nv_bfloat16 g_wqkvTl[QKVD*EMB];
__device__ __nv_bfloat16 g_woutTh[EMB*ATTND];     // w_out^T [N=768][K=768]
__device__ __nv_bfloat16 g_woutTl[EMB*ATTND];
__device__ __nv_bfloat16 g_ah    [MTOT*ATTND];    // attention out hi
__device__ __nv_bfloat16 g_al    [MTOT*ATTND];    // attention out lo

// ---------------------------- helpers --------------------------------------
static __device__ __forceinline__ uint32_t smem_u32(const void* p) {
    uint32_t a;
    asm("{ .reg .u64 t; cvta.to.shared.u64 t, %1; cvt.u32.u64 %0, t; }"
        : "=r"(a) : "l"(p));
    return a;
}

static __device__ __forceinline__ void ldsm4(uint32_t* r, uint32_t addr) {
    asm volatile("ldmatrix.sync.aligned.m8n8.x4.shared.b16 {%0,%1,%2,%3}, [%4];"
                 : "=r"(r[0]), "=r"(r[1]), "=r"(r[2]), "=r"(r[3]) : "r"(addr));
}

static __device__ __forceinline__ void mma_bf16(float* c, const uint32_t* a,
                                                const uint32_t* b) {
    asm volatile(
        "mma.sync.aligned.m16n8k16.row.col.f32.bf16.bf16.f32 "
        "{%0,%1,%2,%3},{%4,%5,%6,%7},{%8,%9},{%0,%1,%2,%3};"
        : "+f"(c[0]), "+f"(c[1]), "+f"(c[2]), "+f"(c[3])
        : "r"(a[0]), "r"(a[1]), "r"(a[2]), "r"(a[3]), "r"(b[0]), "r"(b[1]));
}

// ---------------------------------------------------------------------------
// Split fp32 -> bf16 hi/lo (float4 vectorized). n4 = n/4.
// ---------------------------------------------------------------------------
__global__ void split_kernel(const float* __restrict__ in,
                             __nv_bfloat16* __restrict__ hi,
                             __nv_bfloat16* __restrict__ lo, int n4)
{
    int i = blockIdx.x * blockDim.x + threadIdx.x;
    if (i >= n4) return;
    float4 v = ((const float4*)in)[i];
    union { __nv_bfloat16 b[4]; uint2 u; } H, L;
    H.b[0] = __float2bfloat16(v.x); L.b[0] = __float2bfloat16(v.x - __bfloat162float(H.b[0]));
    H.b[1] = __float2bfloat16(v.y); L.b[1] = __float2bfloat16(v.y - __bfloat162float(H.b[1]));
    H.b[2] = __float2bfloat16(v.z); L.b[2] = __float2bfloat16(v.z - __bfloat162float(H.b[2]));
    H.b[3] = __float2bfloat16(v.w); L.b[3] = __float2bfloat16(v.w - __bfloat162float(H.b[3]));
    ((uint2*)hi)[i] = H.u;
    ((uint2*)lo)[i] = L.u;
}

// ---------------------------------------------------------------------------
// Transpose + split: w[K][N] fp32 -> wT hi/lo [N][K] bf16.
// ---------------------------------------------------------------------------
__global__ void transpose_split(const float* __restrict__ w,
                                __nv_bfloat16* __restrict__ th,
                                __nv_bfloat16* __restrict__ tl, int K, int N)
{
    __shared__ float tile[32][33];
    const int n0 = blockIdx.x * 32;
    const int k0 = blockIdx.y * 32;
    const int tx = threadIdx.x, ty = threadIdx.y; // 32 x 8
    #pragma unroll
    for (int p = 0; p < 4; p++)
        tile[ty + 8*p][tx] = w[(long)(k0 + ty + 8*p) * N + n0 + tx];
    __syncthreads();
    #pragma unroll
    for (int p = 0; p < 4; p++) {
        float f = tile[tx][ty + 8*p];
        __nv_bfloat16 h = __float2bfloat16(f);
        long o = (long)(n0 + ty + 8*p) * K + k0 + tx;
        th[o] = h;
        tl[o] = __float2bfloat16(f - __bfloat162float(h));
    }
}

// ---------------------------------------------------------------------------
// mma.sync split-bf16 GEMM: C[M,N] = A[M,K] * B^T   (B stored [N][K] K-major)
// D = Ah*Bh + Ah*Bl + Al*Bh, fp32 accumulation in registers.
// CTA tile 128x128, BK=32, 8 warps (64x32 each), double-buffered smem.
// smem rows pitched to 80B (64B data + 16B pad) -> ldmatrix conflict-free.
// ---------------------------------------------------------------------------
#define PITCH    80                     // bytes per smem row (32 bf16 + pad)
#define TILE_B   (128*PITCH)            // 10240 B per tile
#define STAGE_B  (4*TILE_B)             // Ah, Al, Bh, Bl = 40960 B
#define GEMM_SMEM (2*STAGE_B)           // 81920 B

__global__ void __launch_bounds__(256, 1)
gemm_mma(const __nv_bfloat16* __restrict__ Ah, const __nv_bfloat16* __restrict__ Al,
         const __nv_bfloat16* __restrict__ Bh, const __nv_bfloat16* __restrict__ Bl,
         float* __restrict__ C, const float* __restrict__ biasp, int N, int K)
{
    extern __shared__ char smem[];
    const int tid  = threadIdx.x;
    const int wid  = tid >> 5;
    const int lane = tid & 31;
    const int wm   = wid >> 2;     // 0..1  (64 rows each)
    const int wn   = wid & 3;      // 0..3  (32 cols each)
    const int bx = blockIdx.x, by = blockIdx.y;

    const uint32_t sbase = smem_u32(smem);

    const char* gsrc[4] = {
        (const char*)(Ah + (long)by * 128 * K),
        (const char*)(Al + (long)by * 128 * K),
        (const char*)(Bh + (long)bx * 128 * K),
        (const char*)(Bl + (long)bx * 128 * K) };
    const long rsb = (long)K * 2;

    // global->smem: per tile 128 rows x 64B; idx -> (row=idx>>2, 16B chunk=idx&3)
    auto load_stage = [&](int s, int k0) {
        char* sb = smem + s * STAGE_B;
        #pragma unroll
        for (int t = 0; t < 4; t++) {
            const char* src = gsrc[t] + (long)k0 * 2;
            char* dst = sb + t * TILE_B;
            #pragma unroll
            for (int i = 0; i < 2; i++) {
                int idx = tid + i * 256;          // 0..511
                int row = idx >> 2;
                int cb  = (idx & 3) * 16;
                uint4 v = *(const uint4*)(src + (long)row * rsb + cb);
                *(uint4*)(dst + row * PITCH + cb) = v;
            }
        }
    };

    // per-thread ldmatrix offsets (bytes)
    const uint32_t a_off = (uint32_t)(wm*64 + (lane & 15)) * PITCH + ((lane >> 4) << 4);
    const uint32_t b_off = (uint32_t)(wn*32 + (lane & 7) + ((lane >> 4) << 3)) * PITCH
                         + (((lane >> 3) & 1) << 4);

    float acc[4][4][4];
    #pragma unroll
    for (int mi = 0; mi < 4; mi++)
        #pragma unroll
        for (int ni = 0; ni < 4; ni++)
            #pragma unroll
            for (int q = 0; q < 4; q++) acc[mi][ni][q] = 0.f;

    const int NI = K / 32;
    load_stage(0, 0);

    for (int it = 0; it < NI; it++) {
        __syncthreads();
        if (it + 1 < NI) load_stage((it + 1) & 1, (it + 1) * 32);

        const uint32_t sb = sbase + (uint32_t)(it & 1) * STAGE_B;
        #pragma unroll
        for (int kh = 0; kh < 2; kh++) {
            uint32_t ah[4][4], al[4][4], bh[2][4], bl[2][4];
            #pragma unroll
            for (int mi = 0; mi < 4; mi++) {
                const uint32_t ao = sb + a_off + mi * (16*PITCH) + kh * 32;
                ldsm4(ah[mi], ao);
                ldsm4(al[mi], ao + TILE_B);
            }
            #pragma unroll
            for (int nj = 0; nj < 2; nj++) {
                const uint32_t bo = sb + 2*TILE_B + b_off + nj * (16*PITCH) + kh * 32;
                ldsm4(bh[nj], bo);
                ldsm4(bl[nj], bo + TILE_B);
            }
            #pragma unroll
            for (int mi = 0; mi < 4; mi++)
                #pragma unroll
                for (int ni = 0; ni < 4; ni++) {
                    const uint32_t* bhp = &bh[ni >> 1][(ni & 1) * 2];
                    const uint32_t* blp = &bl[ni >> 1][(ni & 1) * 2];
                    mma_bf16(acc[mi][ni], ah[mi], bhp);
                    mma_bf16(acc[mi][ni], ah[mi], blp);
                    mma_bf16(acc[mi][ni], al[mi], bhp);
                }
        }
    }

    // Epilogue: fragment layout m16n8 -> rows (lane/4, +8), cols 2*(lane%4)
    const int r0 = by * 128 + wm * 64 + (lane >> 2);
    const int c0 = bx * 128 + wn * 32 + ((lane & 3) << 1);
    #pragma unroll
    for (int mi = 0; mi < 4; mi++) {
        #pragma unroll
        for (int ni = 0; ni < 4; ni++) {
            const int row = r0 + mi * 16;
            const int col = c0 + ni * 8;
            float bx0 = 0.f, bx1 = 0.f;
            if (biasp) { bx0 = biasp[col]; bx1 = biasp[col + 1]; }
            float2 v0 = make_float2(acc[mi][ni][0] + bx0, acc[mi][ni][1] + bx1);
            float2 v1 = make_float2(acc[mi][ni][2] + bx0, acc[mi][ni][3] + bx1);
            *(float2*)(C + (long)row * N + col)       = v0;
            *(float2*)(C + (long)(row + 8) * N + col) = v1;
        }
    }
}

// ---------------------------------------------------------------------------
// Flash attention (fp32 SIMT, passing version; emits bf16 hi/lo)
// ---------------------------------------------------------------------------
__global__ void __launch_bounds__(256)
attn_kernel(const float* __restrict__ qkv,
            __nv_bfloat16* __restrict__ outh, __nv_bfloat16* __restrict__ outl)
{
    const int qt  = blockIdx.x;
    const int h   = blockIdx.y;
    const int b   = blockIdx.z;
    const int tid = threadIdx.x;
    const int tx  = tid & 15;
    const int ty  = tid >> 4;

    extern __shared__ float sm[];
    float* Qt = sm;               // [64][68]
    float* Kt = Qt + 64*68;       // [64][68]
    float* Vs = Kt + 64*68;       // [64][64]
    float* Ps = Vs + 64*64;       // [64][64]

    const float scale = 0.125f;
    const float* Qg = qkv + ((long)b*SEQ + qt*64) * QKVD + h*HDIM;
    const float* Kg = qkv + (long)b*SEQ*QKVD + ATTND   + h*HDIM;
    const float* Vg = qkv + (long)b*SEQ*QKVD + 2*ATTND + h*HDIM;

    {
        const int r = tid >> 4, c = tid & 15;
        #pragma unroll
        for (int p = 0; p < 4; p++) {
            const int row = r + 16*p;
            float4 v = *(const float4*)(Qg + (long)row*QKVD + 4*c);
            Qt[(4*c+0)*68 + row] = v.x;
            Qt[(4*c+1)*68 + row] = v.y;
            Qt[(4*c+2)*68 + row] = v.z;
            Qt[(4*c+3)*68 + row] = v.w;
        }
    }

    float o[4][4];
    float m[4], l[4];
    #pragma unroll
    for (int i = 0; i < 4; i++) {
        m[i] = -1e30f; l[i] = 0.f;
        #pragma unroll
        for (int j = 0; j < 4; j++) o[i][j] = 0.f;
    }

    for (int kt0 = 0; kt0 < SEQ; kt0 += 64) {
        __syncthreads();
        {
            const int r = tid >> 4, c = tid & 15;
            #pragma unroll
            for (int p = 0; p < 4; p++) {
                const int row = r + 16*p;
                float4 k4 = *(const float4*)(Kg + (long)(kt0+row)*QKVD + 4*c);
                Kt[(4*c+0)*68 + row] = k4.x;
                Kt[(4*c+1)*68 + row] = k4.y;
                Kt[(4*c+2)*68 + row] = k4.z;
                Kt[(4*c+3)*68 + row] = k4.w;
                float4 v4 = *(const float4*)(Vg + (long)(kt0+row)*QKVD + 4*c);
                *(float4*)(Vs + row*64 + 4*c) = v4;
            }
        }
        __syncthreads();

        float s[4][4];
        #pragma unroll
        for (int i = 0; i < 4; i++)
            #pragma unroll
            for (int j = 0; j < 4; j++) s[i][j] = 0.f;

        #pragma unroll 8
        for (int d = 0; d < 64; d++) {
            float4 aq = *(const float4*)(Qt + d*68 + 4*ty);
            float4 bk = *(const float4*)(Kt + d*68 + 4*tx);
            const float a_[4] = {aq.x, aq.y, aq.z, aq.w};
            const float b_[4] = {bk.x, bk.y, bk.z, bk.w};
            #pragma unroll
            for (int i = 0; i < 4; i++)
                #pragma unroll
                for (int j = 0; j < 4; j++)
                    s[i][j] = fmaf(a_[i], b_[j], s[i][j]);
        }

        #pragma unroll
        for (int i = 0; i < 4; i++) {
            float tmax = -1e30f;
            #pragma unroll
            for (int j = 0; j < 4; j++) {
                s[i][j] *= scale;
                tmax = fmaxf(tmax, s[i][j]);
            }
            #pragma unroll
            for (int off = 8; off > 0; off >>= 1)
                tmax = fmaxf(tmax, __shfl_xor_sync(0xffffffffu, tmax, off, 16));
            const float newm = fmaxf(m[i], tmax);
            const float corr = __expf(m[i] - newm);
            m[i] = newm;
            l[i] *= corr;
            #pragma unroll
            for (int j = 0; j < 4; j++) o[i][j] *= corr;
            float rs = 0.f;
            #pragma unroll
            for (int j = 0; j < 4; j++) {
                s[i][j] = __expf(s[i][j] - newm);
                rs += s[i][j];
            }
            #pragma unroll
            for (int off = 8; off > 0; off >>= 1)
                rs += __shfl_xor_sync(0xffffffffu, rs, off, 16);
            l[i] += rs;
            *(float4*)(Ps + (4*ty+i)*64 + 4*tx) =
                make_float4(s[i][0], s[i][1], s[i][2], s[i][3]);
        }
        __syncthreads();

        #pragma unroll 4
        for (int k4 = 0; k4 < 16; k4++) {
            float4 pr[4], vr[4];
            #pragma unroll
            for (int i = 0; i < 4; i++)
                pr[i] = *(const float4*)(Ps + (4*ty+i)*64 + 4*k4);
            #pragma unroll
            for (int kk = 0; kk < 4; kk++)
                vr[kk] = *(const float4*)(Vs + (4*k4+kk)*64 + 4*tx);
            #pragma unroll
            for (int i = 0; i < 4; i++) {
                const float p_[4] = {pr[i].x, pr[i].y, pr[i].z, pr[i].w};
                #pragma unroll
                for (int kk = 0; kk < 4; kk++) {
                    const float v_[4] = {vr[kk].x, vr[kk].y, vr[kk].z, vr[kk].w};
                    #pragma unroll
                    for (int j = 0; j < 4; j++)
                        o[i][j] = fmaf(p_[kk], v_[j], o[i][j]);
                }
            }
        }
    }

    const long rbase = ((long)b*SEQ + qt*64) * ATTND + h*HDIM;
    #pragma unroll
    for (int i = 0; i < 4; i++) {
        const float inv = 1.f / l[i];
        float v0 = o[i][0]*inv, v1 = o[i][1]*inv, v2 = o[i][2]*inv, v3 = o[i][3]*inv;
        union { __nv_bfloat16 b[4]; uint2 u; } H, L;
        H.b[0] = __float2bfloat16(v0); L.b[0] = __float2bfloat16(v0 - __bfloat162float(H.b[0]));
        H.b[1] = __float2bfloat16(v1); L.b[1] = __float2bfloat16(v1 - __bfloat162float(H.b[1]));
        H.b[2] = __float2bfloat16(v2); L.b[2] = __float2bfloat16(v2 - __bfloat162float(H.b[2]));
        H.b[3] = __float2bfloat16(v3); L.b[3] = __float2bfloat16(v3 - __bfloat162float(H.b[3]));
        const long off = rbase + (long)(4*ty + i) * ATTND + 4*tx;
        *(uint2*)(outh + off) = H.u;
        *(uint2*)(outl + off) = L.u;
    }
}

// ---------------------------------------------------------------------------
extern "C" void kernel_launch(void* const* d_in, const int* in_sizes, int n_in,
                              void* d_out, int out_size)
{
    const float* x     = (const float*)d_in[0];
    const float* w_qkv = (const float*)d_in[1];
    const float* w_out = (const float*)d_in[2];
    const float* b_out = (const float*)d_in[3];
    float* outp        = (float*)d_out;

    float *qkv_p;
    __nv_bfloat16 *xh_p, *xl_p, *wqh_p, *wql_p, *woh_p, *wol_p, *ah_p, *al_p;
    cudaGetSymbolAddress((void**)&qkv_p, g_qkv);
    cudaGetSymbolAddress((void**)&xh_p,  g_xh);
    cudaGetSymbolAddress((void**)&xl_p,  g_xl);
    cudaGetSymbolAddress((void**)&wqh_p, g_wqkvTh);
    cudaGetSymbolAddress((void**)&wql_p, g_wqkvTl);
    cudaGetSymbolAddress((void**)&woh_p, g_woutTh);
    cudaGetSymbolAddress((void**)&wol_p, g_woutTl);
    cudaGetSymbolAddress((void**)&ah_p,  g_ah);
    cudaGetSymbolAddress((void**)&al_p,  g_al);

    // 0) Conversions
    {
        const int n4 = MTOT * EMB / 4;
        split_kernel<<<(n4 + 255) / 256, 256>>>(x, xh_p, xl_p, n4);
        dim3 tb(32, 8);
        transpose_split<<<dim3(QKVD/32, EMB/32), tb>>>(w_qkv, wqh_p, wql_p, EMB, QKVD);
        transpose_split<<<dim3(EMB/32,  EMB/32), tb>>>(w_out, woh_p, wol_p, EMB, EMB);
    }

    cudaFuncSetAttribute(gemm_mma, cudaFuncAttributeMaxDynamicSharedMemorySize, GEMM_SMEM);

    // 1) QKV projection: [8192,768] x [768,2304]
    gemm_mma<<<dim3(QKVD/128, MTOT/128), 256, GEMM_SMEM>>>(
        xh_p, xl_p, wqh_p, wql_p, qkv_p, nullptr, QKVD, EMB);

    // 2) Attention (fp32 SIMT), emits bf16 hi/lo
    {
        const int smem = (2*64*68 + 2*64*64) * (int)sizeof(float);
        cudaFuncSetAttribute(attn_kernel,
                             cudaFuncAttributeMaxDynamicSharedMemorySize, smem);
        dim3 grid(SEQ/64, NHEADS, BATCH);
        attn_kernel<<<grid, 256, smem>>>(qkv_p, ah_p, al_p);
    }

    // 3) Output projection + bias: [8192,768] x [768,768]
    gemm_mma<<<dim3(EMB/128, MTOT/128), 256, GEMM_SMEM>>>(
        ah_p, al_p, woh_p, wol_p, outp, b_out, EMB, ATTND);
}